// round 5
// baseline (speedup 1.0000x reference)
#include <cuda_runtime.h>
#include <cstdint>

#define T_STEPS 512
#define BATCH   256
#define NINP    128
#define NHID    512
#define KTOT    1152
#define NOUTS   10

#define DT_C    0.042f
#define GAMMA_C 2.7f
#define EPS_C   4.7f

#define JG_N    16
#define BG_N    8
#define NCTA    (JG_N * BG_N)
#define THREADS 256

#define KC          192
#define NCHUNK      6
#define IROW_STRIDE 196
#define WJP_STRIDE  2308
#define W_SH_FLOATS (16 * WJP_STRIDE)
#define I_SH_FLOATS (2 * 32 * IROW_STRIDE)
#define SMEM_BYTES  ((W_SH_FLOATS + I_SH_FLOATS) * 4)

__device__ float    g_hy[2][BATCH][NHID];
__device__ float    g_hz[2][BATCH][NHID];
__device__ unsigned g_bar;

__device__ __forceinline__ unsigned long long dup2(float a) {
    unsigned long long r;
    asm("mov.b64 %0, {%1, %1};" : "=l"(r) : "f"(a));
    return r;
}
__device__ __forceinline__ unsigned long long fma2(unsigned long long a,
                                                   unsigned long long b,
                                                   unsigned long long c) {
    unsigned long long d;
    asm("fma.rn.f32x2 %0, %1, %2, %3;" : "=l"(d) : "l"(a), "l"(b), "l"(c));
    return d;
}
__device__ __forceinline__ float2 unp2(unsigned long long v) {
    float2 r;
    asm("mov.b64 {%0, %1}, %2;" : "=f"(r.x), "=f"(r.y) : "l"(v));
    return r;
}
__device__ __forceinline__ unsigned ld_acq(const unsigned* p) {
    unsigned v;
    asm volatile("ld.acquire.gpu.global.u32 %0, [%1];" : "=r"(v) : "l"(p));
    return v;
}

// Grid barrier: 128 CTAs, all co-resident (grid <= 148 SMs, occupancy 1).
__device__ __forceinline__ void grid_bar(unsigned target) {
    __syncthreads();
    if (threadIdx.x == 0) {
        __threadfence();
        atomicAdd(&g_bar, 1u);
        while (ld_acq(&g_bar) < target) { }
    }
    __syncthreads();
}

// Stage one [32 x KC] chunk of concat(x[t], hz, hy) into shared via cp.async.
__device__ __forceinline__ void stage_chunk(float* buf, int c, int t, int bg,
                                            const float* __restrict__ x,
                                            const float* __restrict__ hzc,
                                            const float* __restrict__ hyc,
                                            int tid) {
    const int kb = c * KC;
    uint32_t sbase = (uint32_t)__cvta_generic_to_shared(buf);
#pragma unroll
    for (int i = 0; i < 6; i++) {          // 32 rows * 48 units of 16B = 1536
        int u   = tid + i * THREADS;
        int row = u / 48;
        int kk  = (u - row * 48) * 4;
        int k   = kb + kk;
        int gr  = bg * 32 + row;
        const float* src;
        if (k < NINP)             src = x   + ((size_t)t * BATCH + gr) * NINP + k;
        else if (k < NINP + NHID) src = hzc + (size_t)gr * NHID + (k - NINP);
        else                      src = hyc + (size_t)gr * NHID + (k - NINP - NHID);
        uint32_t dst = sbase + (uint32_t)((row * IROW_STRIDE + kk) * 4);
        asm volatile("cp.async.ca.shared.global [%0], [%1], 16;" :: "r"(dst), "l"(src));
    }
}

__global__ void cornn_init_kernel() { g_bar = 0u; }

__global__ void __launch_bounds__(THREADS, 1)
cornn_main_kernel(const float* __restrict__ x,    // [T,B,NINP]
                  const float* __restrict__ W,    // [KTOT,NHID]
                  const float* __restrict__ bvec, // [NHID]
                  const float* __restrict__ Wout, // [NHID,NOUTS]
                  const float* __restrict__ bout, // [NOUTS]
                  float* __restrict__ out)        // [B,NOUTS]
{
    extern __shared__ float smem[];
    float* W_sh   = smem;                 // [jp=16][k=1152][2], stride-padded
    float* inp_sh = smem + W_SH_FLOATS;   // 2 x [32][196]

    const int tid = threadIdx.x;
    const int jt  = tid & 7;              // 8 col-threads, 4 cols each
    const int bt  = tid >> 3;             // 32 row-threads
    const int jg  = blockIdx.x;           // 0..15
    const int bg  = blockIdx.y;           // 0..7
    const int jbase = jg * 32;

    // W column slice -> shared, interleaved by column-pairs (once per run)
    for (int idx = tid; idx < KTOT * 32; idx += THREADS) {
        int k = idx >> 5, jc = idx & 31;
        W_sh[(jc >> 1) * WJP_STRIDE + k * 2 + (jc & 1)] =
            W[(size_t)k * NHID + jbase + jc];
    }

    float2 bia0 = make_float2(bvec[jbase + jt * 2],       bvec[jbase + jt * 2 + 1]);
    float2 bia1 = make_float2(bvec[jbase + (jt + 8) * 2], bvec[jbase + (jt + 8) * 2 + 1]);

    // zero state buffer 0 (each CTA zeroes exactly its own tile)
    for (int idx = tid; idx < 1024; idx += THREADS) {
        int r = idx >> 5, jc = idx & 31;
        g_hy[0][bg * 32 + r][jbase + jc] = 0.0f;
        g_hz[0][bg * 32 + r][jbase + jc] = 0.0f;
    }
    unsigned ep = 1;
    grid_bar(ep * NCTA); ep++;

    float2 zo0 = make_float2(0.f, 0.f), zo1 = make_float2(0.f, 0.f);
    float2 yo0 = make_float2(0.f, 0.f), yo1 = make_float2(0.f, 0.f);

    const float* wp0 = W_sh + jt * WJP_STRIDE;
    const float* wp1 = W_sh + (jt + 8) * WJP_STRIDE;
    const int grow = bg * 32 + bt;

    for (int t = 0; t < T_STEPS; t++) {
        const int cur = t & 1, nxt = cur ^ 1;
        const float* hzc = &g_hz[cur][0][0];
        const float* hyc = &g_hy[cur][0][0];

        unsigned long long acc0 = 0ull, acc1 = 0ull;  // packed {+0f,+0f}

        stage_chunk(inp_sh, 0, t, bg, x, hzc, hyc, tid);
        asm volatile("cp.async.commit_group;");

        for (int c = 0; c < NCHUNK; c++) {
            if (c + 1 < NCHUNK) {
                stage_chunk(inp_sh + ((c + 1) & 1) * (32 * IROW_STRIDE),
                            c + 1, t, bg, x, hzc, hyc, tid);
                asm volatile("cp.async.commit_group;");
                asm volatile("cp.async.wait_group 1;");
            } else {
                asm volatile("cp.async.wait_group 0;");
            }
            __syncthreads();

            const float* ib  = inp_sh + (c & 1) * (32 * IROW_STRIDE) + bt * IROW_STRIDE;
            const float* w0c = wp0 + c * KC * 2;
            const float* w1c = wp1 + c * KC * 2;

#pragma unroll 4
            for (int kk = 0; kk < KC; kk += 4) {
                float4 av = *reinterpret_cast<const float4*>(ib + kk);
                ulonglong2 wA = *reinterpret_cast<const ulonglong2*>(w0c + kk * 2);
                ulonglong2 wB = *reinterpret_cast<const ulonglong2*>(w0c + kk * 2 + 4);
                ulonglong2 wC = *reinterpret_cast<const ulonglong2*>(w1c + kk * 2);
                ulonglong2 wD = *reinterpret_cast<const ulonglong2*>(w1c + kk * 2 + 4);
                unsigned long long ax = dup2(av.x), ay = dup2(av.y);
                unsigned long long az = dup2(av.z), aw = dup2(av.w);
                acc0 = fma2(ax, wA.x, acc0);
                acc1 = fma2(ax, wC.x, acc1);
                acc0 = fma2(ay, wA.y, acc0);
                acc1 = fma2(ay, wC.y, acc1);
                acc0 = fma2(az, wB.x, acc0);
                acc1 = fma2(az, wD.x, acc1);
                acc0 = fma2(aw, wB.y, acc0);
                acc1 = fma2(aw, wD.y, acc1);
            }
            __syncthreads();   // buffer (c&1) free before refill
        }

        float2 p0 = unp2(acc0), p1 = unp2(acc1);
        float pre;
        pre = tanhf(p0.x + bia0.x);
        zo0.x += DT_C * (pre - GAMMA_C * yo0.x - EPS_C * zo0.x);  yo0.x += DT_C * zo0.x;
        pre = tanhf(p0.y + bia0.y);
        zo0.y += DT_C * (pre - GAMMA_C * yo0.y - EPS_C * zo0.y);  yo0.y += DT_C * zo0.y;
        pre = tanhf(p1.x + bia1.x);
        zo1.x += DT_C * (pre - GAMMA_C * yo1.x - EPS_C * zo1.x);  yo1.x += DT_C * zo1.x;
        pre = tanhf(p1.y + bia1.y);
        zo1.y += DT_C * (pre - GAMMA_C * yo1.y - EPS_C * zo1.y);  yo1.y += DT_C * zo1.y;

        float* hzn = &g_hz[nxt][grow][jbase];
        float* hyn = &g_hy[nxt][grow][jbase];
        *reinterpret_cast<float2*>(hzn + jt * 2)       = zo0;
        *reinterpret_cast<float2*>(hzn + (jt + 8) * 2) = zo1;
        *reinterpret_cast<float2*>(hyn + jt * 2)       = yo0;
        *reinterpret_cast<float2*>(hyn + (jt + 8) * 2) = yo1;

        grid_bar(ep * NCTA); ep++;
    }

    // Epilogue: out = hy_final @ Wout + bout. Final hy is in buffer 0 (T even).
    if (jg == 0) {
        for (int idx = tid; idx < 32 * NOUTS; idx += THREADS) {
            int r = idx / NOUTS, oc = idx - r * NOUTS;
            const float* hp = &g_hy[0][bg * 32 + r][0];
            float s = bout[oc];
#pragma unroll 8
            for (int k = 0; k < NHID; k++)
                s += hp[k] * Wout[(size_t)k * NOUTS + oc];
            out[(size_t)(bg * 32 + r) * NOUTS + oc] = s;
        }
    }
}

extern "C" void kernel_launch(void* const* d_in, const int* in_sizes, int n_in,
                              void* d_out, int out_size) {
    const float* x    = (const float*)d_in[0];
    const float* W    = (const float*)d_in[1];
    const float* b    = (const float*)d_in[2];
    const float* Wout = (const float*)d_in[3];
    const float* bout = (const float*)d_in[4];
    float* out = (float*)d_out;

    static bool attr_set = false;  // attribute config only; work is unconditional
    if (!attr_set) {
        cudaFuncSetAttribute(cornn_main_kernel,
                             cudaFuncAttributeMaxDynamicSharedMemorySize, SMEM_BYTES);
        attr_set = true;
    }

    cornn_init_kernel<<<1, 1>>>();
    dim3 grid(JG_N, BG_N);
    cornn_main_kernel<<<grid, THREADS, SMEM_BYTES>>>(x, W, b, Wout, bout, out);
}

// round 6
// speedup vs baseline: 1.0006x; 1.0006x over previous
#include <cuda_runtime.h>
#include <cstdint>

#define T_STEPS 512
#define BATCH   256
#define NINP    128
#define NHID    512
#define KTOT    1152
#define NOUTS   10

#define DT_C    0.042f
#define GAMMA_C 2.7f
#define EPS_C   4.7f

#define JG_N    16
#define BG_N    8
#define NCTA    (JG_N * BG_N)
#define THREADS 256

#define KC          192
#define NCHUNK      6
#define IROW_STRIDE 196
#define WJP_STRIDE  2308
#define W_SH_FLOATS (16 * WJP_STRIDE)
#define I_SH_FLOATS (2 * 32 * IROW_STRIDE)
#define SMEM_BYTES  ((W_SH_FLOATS + I_SH_FLOATS) * 4)

__device__ float    g_hy[2][BATCH][NHID];
__device__ float    g_hz[2][BATCH][NHID];
__device__ unsigned g_bar;

__device__ __forceinline__ unsigned long long dup2(float a) {
    unsigned long long r;
    asm("mov.b64 %0, {%1, %1};" : "=l"(r) : "f"(a));
    return r;
}
__device__ __forceinline__ unsigned long long fma2(unsigned long long a,
                                                   unsigned long long b,
                                                   unsigned long long c) {
    unsigned long long d;
    asm("fma.rn.f32x2 %0, %1, %2, %3;" : "=l"(d) : "l"(a), "l"(b), "l"(c));
    return d;
}
__device__ __forceinline__ float2 unp2(unsigned long long v) {
    float2 r;
    asm("mov.b64 {%0, %1}, %2;" : "=f"(r.x), "=f"(r.y) : "l"(v));
    return r;
}
__device__ __forceinline__ unsigned ld_acq(const unsigned* p) {
    unsigned v;
    asm volatile("ld.acquire.gpu.global.u32 %0, [%1];" : "=r"(v) : "l"(p));
    return v;
}

// Grid barrier: 128 CTAs, all co-resident (grid <= 148 SMs, occupancy 1).
__device__ __forceinline__ void grid_bar(unsigned target) {
    __syncthreads();
    if (threadIdx.x == 0) {
        __threadfence();
        atomicAdd(&g_bar, 1u);
        while (ld_acq(&g_bar) < target) { }
    }
    __syncthreads();
}

// Stage one [32 x KC] chunk of concat(x[t], hz, hy) into shared via cp.async.
__device__ __forceinline__ void stage_chunk(float* buf, int c, int t, int bg,
                                            const float* __restrict__ x,
                                            const float* __restrict__ hzc,
                                            const float* __restrict__ hyc,
                                            int tid) {
    const int kb = c * KC;
    uint32_t sbase = (uint32_t)__cvta_generic_to_shared(buf);
#pragma unroll
    for (int i = 0; i < 6; i++) {          // 32 rows * 48 units of 16B = 1536
        int u   = tid + i * THREADS;
        int row = u / 48;
        int kk  = (u - row * 48) * 4;
        int k   = kb + kk;
        int gr  = bg * 32 + row;
        const float* src;
        if (k < NINP)             src = x   + ((size_t)t * BATCH + gr) * NINP + k;
        else if (k < NINP + NHID) src = hzc + (size_t)gr * NHID + (k - NINP);
        else                      src = hyc + (size_t)gr * NHID + (k - NINP - NHID);
        uint32_t dst = sbase + (uint32_t)((row * IROW_STRIDE + kk) * 4);
        asm volatile("cp.async.ca.shared.global [%0], [%1], 16;" :: "r"(dst), "l"(src));
    }
}

__global__ void cornn_init_kernel() { g_bar = 0u; }

__global__ void __launch_bounds__(THREADS, 1)
cornn_main_kernel(const float* __restrict__ x,    // [T,B,NINP]
                  const float* __restrict__ W,    // [KTOT,NHID]
                  const float* __restrict__ bvec, // [NHID]
                  const float* __restrict__ Wout, // [NHID,NOUTS]
                  const float* __restrict__ bout, // [NOUTS]
                  float* __restrict__ out)        // [B,NOUTS]
{
    extern __shared__ float smem[];
    float* W_sh   = smem;                 // [jp=16][k=1152][2], stride-padded
    float* inp_sh = smem + W_SH_FLOATS;   // 2 x [32][196]

    const int tid = threadIdx.x;
    const int jt  = tid & 7;              // 8 col-threads, 4 cols each
    const int bt  = tid >> 3;             // 32 row-threads
    const int jg  = blockIdx.x;           // 0..15
    const int bg  = blockIdx.y;           // 0..7
    const int jbase = jg * 32;

    // W column slice -> shared, interleaved by column-pairs (once per run)
    for (int idx = tid; idx < KTOT * 32; idx += THREADS) {
        int k = idx >> 5, jc = idx & 31;
        W_sh[(jc >> 1) * WJP_STRIDE + k * 2 + (jc & 1)] =
            W[(size_t)k * NHID + jbase + jc];
    }

    float2 bia0 = make_float2(bvec[jbase + jt * 2],       bvec[jbase + jt * 2 + 1]);
    float2 bia1 = make_float2(bvec[jbase + (jt + 8) * 2], bvec[jbase + (jt + 8) * 2 + 1]);

    // zero state buffer 0 (each CTA zeroes exactly its own tile)
    for (int idx = tid; idx < 1024; idx += THREADS) {
        int r = idx >> 5, jc = idx & 31;
        g_hy[0][bg * 32 + r][jbase + jc] = 0.0f;
        g_hz[0][bg * 32 + r][jbase + jc] = 0.0f;
    }
    unsigned ep = 1;
    grid_bar(ep * NCTA); ep++;

    float2 zo0 = make_float2(0.f, 0.f), zo1 = make_float2(0.f, 0.f);
    float2 yo0 = make_float2(0.f, 0.f), yo1 = make_float2(0.f, 0.f);

    const float* wp0 = W_sh + jt * WJP_STRIDE;
    const float* wp1 = W_sh + (jt + 8) * WJP_STRIDE;
    const int grow = bg * 32 + bt;

    for (int t = 0; t < T_STEPS; t++) {
        const int cur = t & 1, nxt = cur ^ 1;
        const float* hzc = &g_hz[cur][0][0];
        const float* hyc = &g_hy[cur][0][0];

        unsigned long long acc0 = 0ull, acc1 = 0ull;  // packed {+0f,+0f}

        stage_chunk(inp_sh, 0, t, bg, x, hzc, hyc, tid);
        asm volatile("cp.async.commit_group;");

        for (int c = 0; c < NCHUNK; c++) {
            if (c + 1 < NCHUNK) {
                stage_chunk(inp_sh + ((c + 1) & 1) * (32 * IROW_STRIDE),
                            c + 1, t, bg, x, hzc, hyc, tid);
                asm volatile("cp.async.commit_group;");
                asm volatile("cp.async.wait_group 1;");
            } else {
                asm volatile("cp.async.wait_group 0;");
            }
            __syncthreads();

            const float* ib  = inp_sh + (c & 1) * (32 * IROW_STRIDE) + bt * IROW_STRIDE;
            const float* w0c = wp0 + c * KC * 2;
            const float* w1c = wp1 + c * KC * 2;

#pragma unroll 4
            for (int kk = 0; kk < KC; kk += 4) {
                float4 av = *reinterpret_cast<const float4*>(ib + kk);
                ulonglong2 wA = *reinterpret_cast<const ulonglong2*>(w0c + kk * 2);
                ulonglong2 wB = *reinterpret_cast<const ulonglong2*>(w0c + kk * 2 + 4);
                ulonglong2 wC = *reinterpret_cast<const ulonglong2*>(w1c + kk * 2);
                ulonglong2 wD = *reinterpret_cast<const ulonglong2*>(w1c + kk * 2 + 4);
                unsigned long long ax = dup2(av.x), ay = dup2(av.y);
                unsigned long long az = dup2(av.z), aw = dup2(av.w);
                acc0 = fma2(ax, wA.x, acc0);
                acc1 = fma2(ax, wC.x, acc1);
                acc0 = fma2(ay, wA.y, acc0);
                acc1 = fma2(ay, wC.y, acc1);
                acc0 = fma2(az, wB.x, acc0);
                acc1 = fma2(az, wD.x, acc1);
                acc0 = fma2(aw, wB.y, acc0);
                acc1 = fma2(aw, wD.y, acc1);
            }
            __syncthreads();   // buffer (c&1) free before refill
        }

        float2 p0 = unp2(acc0), p1 = unp2(acc1);
        float pre;
        pre = tanhf(p0.x + bia0.x);
        zo0.x += DT_C * (pre - GAMMA_C * yo0.x - EPS_C * zo0.x);  yo0.x += DT_C * zo0.x;
        pre = tanhf(p0.y + bia0.y);
        zo0.y += DT_C * (pre - GAMMA_C * yo0.y - EPS_C * zo0.y);  yo0.y += DT_C * zo0.y;
        pre = tanhf(p1.x + bia1.x);
        zo1.x += DT_C * (pre - GAMMA_C * yo1.x - EPS_C * zo1.x);  yo1.x += DT_C * zo1.x;
        pre = tanhf(p1.y + bia1.y);
        zo1.y += DT_C * (pre - GAMMA_C * yo1.y - EPS_C * zo1.y);  yo1.y += DT_C * zo1.y;

        float* hzn = &g_hz[nxt][grow][jbase];
        float* hyn = &g_hy[nxt][grow][jbase];
        *reinterpret_cast<float2*>(hzn + jt * 2)       = zo0;
        *reinterpret_cast<float2*>(hzn + (jt + 8) * 2) = zo1;
        *reinterpret_cast<float2*>(hyn + jt * 2)       = yo0;
        *reinterpret_cast<float2*>(hyn + (jt + 8) * 2) = yo1;

        grid_bar(ep * NCTA); ep++;
    }

    // Epilogue: out = hy_final @ Wout + bout. Final hy is in buffer 0 (T even).
    if (jg == 0) {
        for (int idx = tid; idx < 32 * NOUTS; idx += THREADS) {
            int r = idx / NOUTS, oc = idx - r * NOUTS;
            const float* hp = &g_hy[0][bg * 32 + r][0];
            float s = bout[oc];
#pragma unroll 8
            for (int k = 0; k < NHID; k++)
                s += hp[k] * Wout[(size_t)k * NOUTS + oc];
            out[(size_t)(bg * 32 + r) * NOUTS + oc] = s;
        }
    }
}

extern "C" void kernel_launch(void* const* d_in, const int* in_sizes, int n_in,
                              void* d_out, int out_size) {
    const float* x    = (const float*)d_in[0];
    const float* W    = (const float*)d_in[1];
    const float* b    = (const float*)d_in[2];
    const float* Wout = (const float*)d_in[3];
    const float* bout = (const float*)d_in[4];
    float* out = (float*)d_out;

    static bool attr_set = false;  // attribute config only; work is unconditional
    if (!attr_set) {
        cudaFuncSetAttribute(cornn_main_kernel,
                             cudaFuncAttributeMaxDynamicSharedMemorySize, SMEM_BYTES);
        attr_set = true;
    }

    cornn_init_kernel<<<1, 1>>>();
    dim3 grid(JG_N, BG_N);
    cornn_main_kernel<<<grid, THREADS, SMEM_BYTES>>>(x, W, b, Wout, bout, out);
}